// round 16
// baseline (speedup 1.0000x reference)
#include <cuda_runtime.h>
#include <cstdint>

#define N_PATHS 65536
#define N_STEPS 512

// piecewise-cubic lambda table: 24 segments per step, 4 nodes per segment
#define NSEG    24
#define TILE    32
#define PAD     3        // row stride TILE+3 = 35: bank 3l+si, gcd(3,32)=1 -> conflict-free

#define TPB1    96      // phase-1: one step per block (validated R15)
#define TPB2    64
#define WARPS2  (TPB2/32)

// ---- constants (match reference float32 semantics) ----
#define DT_F        (1.0f/252.0f)
#define SQRT_DT_F   0.06299407883487120f     // sqrt(1/252)
#define KAPPA_F     2.72f
#define THETA_F     (-3.5f)
#define SIGMA_P_F   0.85f
#define RHO_F       (-0.85f)
#define CS_F        (0.5267826876426369f * 0.06299407883487120f) // sqrt(1-rho^2)*sqrt_dt
#define R_F         0.0373f
#define LAMBDA_MAX_F 3.0f
#define LOG_V_MIN_F (-7.0f)
#define LOG_V_MAX_F 2.0f
#define INV_NSTEPS  (1.0f/512.0f)
#define SEG_H       ((LOG_V_MAX_F - LOG_V_MIN_F) / (float)NSEG)      // 9/24
#define SEG_SCALE   ((float)NSEG / (LOG_V_MAX_F - LOG_V_MIN_F))      // 24/9
#define SEG_OFS     (-(LOG_V_MIN_F) * SEG_SCALE)
#define SEG_LIM     ((float)NSEG - 0.001f)
// drift restructure: lv + kappa*(theta-lv)*dt = A*lv + B
#define DRIFT_A     (1.0f - KAPPA_F * DT_F)
#define DRIFT_B     (KAPPA_F * THETA_F * DT_F)
#define NEG_SGDT    (-(SIGMA_P_F * DT_F))
#define SIGP_SQDT   (SIGMA_P_F * SQRT_DT_F)

// scratch (device global = legal scratch)
__device__ float4 g_coef[N_STEPS * NSEG];         // monomial cubic coeffs per segment

typedef unsigned long long ull;

// ---- packed f32x2 helpers (Blackwell fma.rn.f32x2) ----
__device__ __forceinline__ ull pack2(float a, float b) {
    ull r; asm("mov.b64 %0, {%1, %2};" : "=l"(r) : "f"(a), "f"(b)); return r;
}
__device__ __forceinline__ void unpack2(ull v, float& a, float& b) {
    asm("mov.b64 {%0, %1}, %2;" : "=f"(a), "=f"(b) : "l"(v));
}
__device__ __forceinline__ ull fma2(ull a, ull b, ull c) {
    ull d; asm("fma.rn.f32x2 %0, %1, %2, %3;" : "=l"(d) : "l"(a), "l"(b), "l"(c)); return d;
}
__device__ __forceinline__ ull mul2(ull a, ull b) {
    ull d; asm("mul.rn.f32x2 %0, %1, %2;" : "=l"(d) : "l"(a), "l"(b)); return d;
}

__device__ __forceinline__ float fast_tanh(float x) {
    float y;
    asm("tanh.approx.f32 %0, %1;" : "=f"(y) : "f"(x));
    return y;
}

// 5-op gelu on a pair (validated): gelu(x)=fma(0.5x, tanh(u), 0.5x)
__device__ __forceinline__ ull gelu2(ull x, ull GA, ull GB, ull GH) {
    ull x2 = mul2(x, x);
    ull u  = mul2(x, fma2(GA, x2, GB));
    ull hx = mul2(GH, x);
    float ulo, uhi; unpack2(u, ulo, uhi);
    ull tp = pack2(fast_tanh(ulo), fast_tanh(uhi));
    return fma2(hx, tp, hx);
}

__device__ __forceinline__ float clipf(float v) {
    return fminf(fmaxf(v, LOG_V_MIN_F), LOG_V_MAX_F);
}

// ============================================================================
// Phase 1 (fused, validated R15): lambda at segment nodes + cubic coeffs.
// One block = one time step, 96 threads.
// ============================================================================
__global__ __launch_bounds__(TPB1, 4)
void node_kernel(const float* __restrict__ W1,  const float* __restrict__ b1,
                 const float* __restrict__ W2,  const float* __restrict__ b2,
                 const float* __restrict__ W3,  const float* __restrict__ b3)
{
    __shared__ float sw1t[32], sb1[32];
    __shared__ ull   sw0d[32], sb2d[32], sw3d[32];
    __shared__ __align__(16) float sW2[1024];
    __shared__ float sb3s;

    const int tid = threadIdx.x;
    for (int i = tid; i < 1024; i += TPB1) sW2[i] = W2[i];
    if (tid < 32) {
        float w0 = W1[2 * tid];
        sw0d[tid] = pack2(w0, w0);
        sw1t[tid] = W1[2 * tid + 1];
        sb1[tid]  = b1[tid];
        float bb = b2[tid];
        sb2d[tid] = pack2(bb, bb);
        float w3 = W3[tid];
        sw3d[tid] = pack2(w3, w3);
    }
    if (tid == 0) sb3s = b3[0];
    __syncthreads();

    const float4* W2v = reinterpret_cast<const float4*>(sW2);
    const ull GA = pack2(0.0356774081363059f, 0.0356774081363059f);
    const ull GB = pack2(0.7978845608028654f, 0.7978845608028654f);
    const ull GH = pack2(0.5f, 0.5f);

    const int s    = blockIdx.x;              // time step
    const int j    = tid >> 2;                // segment 0..23
    const int p    = (tid >> 1) & 1;          // node parity
    const int half = tid & 1;                 // group-half
    const float t = (float)s * INV_NSTEPS;

    const float lvA = fmaf((float)j + (float)p * 0.3333333333f, SEG_H, LOG_V_MIN_F);
    const float lvB = lvA + 0.6666666666f * SEG_H;
    const ull lvp = pack2(lvA, lvB);

    ull h1[32];
    #pragma unroll
    for (int k = 0; k < 32; k++) {
        float c1 = fmaf(sw1t[k], t, sb1[k]);
        ull arg = fma2(sw0d[k], lvp, pack2(c1, c1));
        h1[k] = gelu2(arg, GA, GB, GH);
    }

    ull red0 = pack2(0.0f, 0.0f);
    ull red1 = pack2(0.0f, 0.0f);
    #pragma unroll 1
    for (int jg = half * 4; jg < half * 4 + 4; jg++) {
        const int j0 = jg * 4;
        ull a0 = sb2d[j0 + 0];
        ull a1 = sb2d[j0 + 1];
        ull a2 = sb2d[j0 + 2];
        ull a3 = sb2d[j0 + 3];
        #pragma unroll
        for (int k4 = 0; k4 < 8; k4++) {
            ull h0 = h1[4 * k4 + 0];
            ull hA = h1[4 * k4 + 1];
            ull hB = h1[4 * k4 + 2];
            ull hC = h1[4 * k4 + 3];
            float4 q0 = W2v[(j0 + 0) * 8 + k4];
            float4 q1 = W2v[(j0 + 1) * 8 + k4];
            float4 q2 = W2v[(j0 + 2) * 8 + k4];
            float4 q3 = W2v[(j0 + 3) * 8 + k4];
            a0 = fma2(pack2(q0.x, q0.x), h0, a0);
            a0 = fma2(pack2(q0.y, q0.y), hA, a0);
            a0 = fma2(pack2(q0.z, q0.z), hB, a0);
            a0 = fma2(pack2(q0.w, q0.w), hC, a0);
            a1 = fma2(pack2(q1.x, q1.x), h0, a1);
            a1 = fma2(pack2(q1.y, q1.y), hA, a1);
            a1 = fma2(pack2(q1.z, q1.z), hB, a1);
            a1 = fma2(pack2(q1.w, q1.w), hC, a1);
            a2 = fma2(pack2(q2.x, q2.x), h0, a2);
            a2 = fma2(pack2(q2.y, q2.y), hA, a2);
            a2 = fma2(pack2(q2.z, q2.z), hB, a2);
            a2 = fma2(pack2(q2.w, q2.w), hC, a2);
            a3 = fma2(pack2(q3.x, q3.x), h0, a3);
            a3 = fma2(pack2(q3.y, q3.y), hA, a3);
            a3 = fma2(pack2(q3.z, q3.z), hB, a3);
            a3 = fma2(pack2(q3.w, q3.w), hC, a3);
        }
        red0 = fma2(sw3d[j0 + 0], gelu2(a0, GA, GB, GH), red0);
        red1 = fma2(sw3d[j0 + 1], gelu2(a1, GA, GB, GH), red1);
        red0 = fma2(sw3d[j0 + 2], gelu2(a2, GA, GB, GH), red0);
        red1 = fma2(sw3d[j0 + 3], gelu2(a3, GA, GB, GH), red1);
    }
    float rA0, rB0, rA1, rB1;
    unpack2(red0, rA0, rB0);
    unpack2(red1, rA1, rB1);
    float sumA = rA0 + rA1;
    float sumB = rB0 + rB1;
    sumA += __shfl_xor_sync(0xffffffffu, sumA, 1);
    sumB += __shfl_xor_sync(0xffffffffu, sumB, 1);
    float lamA = LAMBDA_MAX_F * tanhf(sumA + sb3s);   // u = p/3
    float lamB = LAMBDA_MAX_F * tanhf(sumB + sb3s);   // u = p/3 + 2/3

    float oA = __shfl_xor_sync(0xffffffffu, lamA, 2);
    float oB = __shfl_xor_sync(0xffffffffu, lamB, 2);
    if ((tid & 3) == 0) {
        float f0 = lamA, f2 = lamB;   // own: u = 0, 2/3
        float f1 = oA,   f3 = oB;     // partner: u = 1/3, 1
        float4 c;
        c.x = f0;
        c.y = 0.5f * (-11.0f * f0 + 18.0f * f1 - 9.0f  * f2 + 2.0f * f3);
        c.z = 0.5f * ( 18.0f * f0 - 45.0f * f1 + 36.0f * f2 - 9.0f * f3);
        c.w = 0.5f * ( -9.0f * f0 + 27.0f * f1 - 27.0f * f2 + 9.0f * f3);
        g_coef[s * NSEG + j] = c;
    }
}

// ============================================================================
// Phase 2: SDE sweep with a DEPTH-2 SOFTWARE-PIPELINED lambda gather.
// lambda's weight on lv is sigma*dt = 0.0034 (|delta lv| <= 0.0102 = 3% of a
// segment), so the segment INDEX for steps s+1/s+2 is computed from the
// lambda-free drift approximation (clip(base), clip(A*clip(base)+e_next)).
// The fetched cubic is evaluated at the TRUE u (possibly in [-0.06,1.06]);
// C0 continuity at shared nodes makes the off-segment error ~1e-6.
// Per-step serial chain: u=fma -> Horner(3 fma) -> fma -> clip -> fma(base).
// The full gather (clip,F2I,LDS.128,I2F) runs 2 steps ahead, off-chain.
// z values rotate one step ahead through registers (also feed e_next).
// ============================================================================
__global__ __launch_bounds__(TPB2, 7)
void sde_kernel(const float* __restrict__ z1, const float* __restrict__ z2,
                const float* __restrict__ init_log_v,
                float* __restrict__ out)
{
    __shared__ float sza[WARPS2][32][TILE + PAD];        // z1 in -> log_v out
    __shared__ float szb[WARPS2][32][TILE + PAD];        // z2 in -> spot  out
    __shared__ __align__(16) float4 scoef[TILE][NSEG];   // 12 KB coeff tile

    const int tid = threadIdx.x;
    const int w = tid >> 5;
    const int l = tid & 31;
    const int pbase = blockIdx.x * TPB2 + w * 32;

    const int h = l >> 3;          // path sub-index 0..3
    const int m = l & 7;           // 16B chunk 0..7
    const int sc = m * 4;

    const float* z1w = z1 + (size_t)pbase * N_STEPS;
    const float* z2w = z2 + (size_t)pbase * N_STEPS;
    float* out_lv = out;
    float* out_sp = out + (size_t)N_PATHS * N_STEPS;
    float* out_lq = out + 2 * (size_t)N_PATHS * N_STEPS;

    float lv  = init_log_v[0];
    float ls  = 0.0f;
    float lsq = 0.0f;

    // ---- initial prefetch (tile 0): full-line z loads, L2-only ----
    float4 r1[8], r2[8];
    #pragma unroll
    for (int i = 0; i < 8; i++) {
        int pr = i * 4 + h;
        r1[i] = __ldcg(reinterpret_cast<const float4*>(z1w + (size_t)pr * N_STEPS + sc));
        r2[i] = __ldcg(reinterpret_cast<const float4*>(z2w + (size_t)pr * N_STEPS + sc));
    }

    #pragma unroll 1
    for (int s0 = 0; s0 < N_STEPS; s0 += TILE) {
        __syncthreads();   // previous tile's smem reads complete

        // ---- deposit prefetched z into padded smem (conflict-free) ----
        #pragma unroll
        for (int i = 0; i < 8; i++) {
            int pr = i * 4 + h;
            sza[w][pr][sc]     = r1[i].x; sza[w][pr][sc + 1] = r1[i].y;
            sza[w][pr][sc + 2] = r1[i].z; sza[w][pr][sc + 3] = r1[i].w;
            szb[w][pr][sc]     = r2[i].x; szb[w][pr][sc + 1] = r2[i].y;
            szb[w][pr][sc + 2] = r2[i].z; szb[w][pr][sc + 3] = r2[i].w;
        }

        // ---- refill coeff tile: 32 steps x 24 float4 = 768 float4 ----
        {
            const float4* src = g_coef + (size_t)s0 * NSEG;
            float4* dst = &scoef[0][0];
            #pragma unroll
            for (int i = 0; i < (TILE * NSEG) / TPB2; i++)   // 12 per thread
                dst[tid + i * TPB2] = src[tid + i * TPB2];
        }

        // ---- issue NEXT tile's z loads (latency hidden under step loop) ----
        if (s0 + TILE < N_STEPS) {
            #pragma unroll
            for (int i = 0; i < 8; i++) {
                int pr = i * 4 + h;
                r1[i] = __ldcg(reinterpret_cast<const float4*>(z1w + (size_t)pr * N_STEPS + s0 + TILE + sc));
                r2[i] = __ldcg(reinterpret_cast<const float4*>(z2w + (size_t)pr * N_STEPS + s0 + TILE + sc));
            }
        }
        __syncthreads();   // z + coef tiles visible to all

        // ---- pipeline bootstrap: z for steps 0,1 and coef for steps 0,1 ----
        float zc1 = sza[w][l][0], zc2 = szb[w][l][0];
        float zn1 = sza[w][l][1], zn2 = szb[w][l][1];

        float  x0 = fminf(fmaf(lv, SEG_SCALE, SEG_OFS), SEG_LIM);
        int    j0 = __float2int_rd(x0);
        float4 c0 = scoef[0][j0];
        float  o0 = SEG_OFS - (float)j0;

        float e0    = fmaf(SIGP_SQDT, zc1, DRIFT_B);
        float lvap1 = clipf(fmaf(DRIFT_A, lv, e0));          // ~ lv at step 1
        float  x1 = fminf(fmaf(lvap1, SEG_SCALE, SEG_OFS), SEG_LIM);
        int    j1 = __float2int_rd(x1);
        float4 c1 = scoef[1][j1];
        float  o1 = SEG_OFS - (float)j1;

        // ---- 32 sequential SDE steps, gather pipelined 2 ahead ----
        #pragma unroll 8
        for (int si = 0; si < TILE; si++) {
            float dwv = SQRT_DT_F * zc1;
            float dws = fmaf(RHO_F, dwv, CS_F * zc2);
            float e   = fmaf(SIGMA_P_F, dwv, DRIFT_B);

            // short chain: u -> Horner -> lam -> lv_next (gather already done)
            float u   = fmaf(lv, SEG_SCALE, o0);
            float lam = fmaf(fmaf(fmaf(c0.w, u, c0.z), u, c0.y), u, c0.x);
            float base = fmaf(DRIFT_A, lv, e);
            float lv_next = clipf(fmaf(lam, NEG_SGDT, base));

            // outputs (off chain)
            float vol = __expf(0.5f * lv);
            float ev  = vol * vol;
            float ls_next = fmaf(vol, dws, fmaf(ev, -0.5f * DT_F, ls + R_F * DT_F));
            lsq = fmaf(lam * lam, DT_F, lsq);
            sza[w][l][si] = lv_next;
            szb[w][l][si] = __expf(ls_next);

            // rotate z one ahead (slot si+2 <= TILE+1 is in-bounds w/ PAD=3)
            float za = sza[w][l][si + 2];
            float zb = szb[w][l][si + 2];

            // prefetch coef for step si+2 from the lambda-free approximation
            float4 cn = c1; float on = o1;
            if (si + 2 < TILE) {
                float en    = fmaf(SIGP_SQDT, zn1, DRIFT_B);     // e of step si+1
                float lvap  = clipf(base);                       // ~ lv at si+1
                float lvap2 = clipf(fmaf(DRIFT_A, lvap, en));    // ~ lv at si+2
                float xn = fminf(fmaf(lvap2, SEG_SCALE, SEG_OFS), SEG_LIM);
                int   jn = __float2int_rd(xn);
                cn = scoef[si + 2][jn];
                on = SEG_OFS - (float)jn;
            }
            c0 = c1; o0 = o1;
            c1 = cn; o1 = on;
            zc1 = zn1; zc2 = zn2;
            zn1 = za;  zn2 = zb;

            lv = lv_next;
            ls = ls_next;
        }
        __syncwarp();   // own-warp sza/szb writes visible before flush

        // ---- flush outputs: full-line STG.128, L2-only ----
        #pragma unroll
        for (int i = 0; i < 8; i++) {
            int pr = i * 4 + h;
            float4 ov, os;
            ov.x = sza[w][pr][sc];     ov.y = sza[w][pr][sc + 1];
            ov.z = sza[w][pr][sc + 2]; ov.w = sza[w][pr][sc + 3];
            os.x = szb[w][pr][sc];     os.y = szb[w][pr][sc + 1];
            os.z = szb[w][pr][sc + 2]; os.w = szb[w][pr][sc + 3];
            __stcg(reinterpret_cast<float4*>(out_lv + (size_t)(pbase + pr) * N_STEPS + s0 + sc), ov);
            __stcg(reinterpret_cast<float4*>(out_sp + (size_t)(pbase + pr) * N_STEPS + s0 + sc), os);
        }
    }

    out_lq[pbase + l] = lsq;
}

extern "C" void kernel_launch(void* const* d_in, const int* in_sizes, int n_in,
                              void* d_out, int out_size)
{
    (void)in_sizes; (void)n_in; (void)out_size;
    // Phase 1 (fused): lambda nodes + cubic coefficients, one block per step
    node_kernel<<<N_STEPS, TPB1>>>(
        (const float*)d_in[2], (const float*)d_in[3],
        (const float*)d_in[4], (const float*)d_in[5],
        (const float*)d_in[6], (const float*)d_in[7]);
    // Phase 2: SDE sweep with pipelined piecewise-cubic lambda
    sde_kernel<<<N_PATHS / TPB2, TPB2>>>(
        (const float*)d_in[0], (const float*)d_in[1],
        (const float*)d_in[8],
        (float*)d_out);
}